// round 14
// baseline (speedup 1.0000x reference)
#include <cuda_runtime.h>
#include <cstdint>

#define T_DATA 100000
#define N_E    500
#define N_I    200
#define SUB    20
#define NB     3
#define TSYN   201

typedef unsigned long long ull;

// ---- GEMM config ----
#define GTH    256                 // 8 warps x 16 rows = 128 rows/block
#define SSTR   36                  // smem row stride in words (== 4 mod 32)
#define S_WORDS (128 * SSTR)       // 4608 floats per S buffer
#define C_WORDS (24 * SSTR)        // 864 floats per C buffer

// ---- conv config ----
#define CTH   128
#define TTC   1024
#define KP    208
#define NWC   154

// ---- pipeline split (gemm rows 128/blk, conv tiles 1024/blk) ----
#define NSPLIT 4

// Scratch (device globals: allocation-free rule)
__device__ float g_e[(size_t)SUB * T_DATA];
__device__ float g_i[(size_t)SUB * T_DATA];

// ---- packed f32x2 helpers (conv) ----
__device__ __forceinline__ ull pk2(float lo, float hi) {
    ull r;
    asm("mov.b64 %0, {%1, %2};" : "=l"(r) : "f"(lo), "f"(hi));
    return r;
}
__device__ __forceinline__ void upk2(ull v, float& lo, float& hi) {
    asm("mov.b64 {%0, %1}, %2;" : "=f"(lo), "=f"(hi) : "l"(v));
}
__device__ __forceinline__ void fma2(ull& d, ull a, ull b) {
    asm("fma.rn.f32x2 %0, %1, %2, %0;" : "+l"(d) : "l"(a), "l"(b));
}

// ---- GEMM helpers ----
__device__ __forceinline__ uint32_t smem_u32(const void* p) {
    return (uint32_t)__cvta_generic_to_shared(p);
}
__device__ __forceinline__ void cpa16(uint32_t dst, const void* src, bool ok) {
    int sz = ok ? 16 : 0;
    asm volatile("cp.async.cg.shared.global [%0], [%1], 16, %2;"
                 :: "r"(dst), "l"(src), "r"(sz));
}
__device__ __forceinline__ uint32_t to_tf32(float f) {
    uint32_t u;
    asm("cvt.rna.tf32.f32 %0, %1;" : "=r"(u) : "f"(f));
    return u;
}
__device__ __forceinline__ void mma_tf32(float* d, uint32_t a0, uint32_t a1,
                                         uint32_t a2, uint32_t a3,
                                         uint32_t b0, uint32_t b1) {
    asm volatile(
        "mma.sync.aligned.m16n8k8.row.col.f32.tf32.tf32.f32 "
        "{%0,%1,%2,%3}, {%4,%5,%6,%7}, {%8,%9}, {%0,%1,%2,%3};"
        : "+f"(d[0]), "+f"(d[1]), "+f"(d[2]), "+f"(d[3])
        : "r"(a0), "r"(a1), "r"(a2), "r"(a3), "r"(b0), "r"(b1));
}

// ---------------------------------------------------------------------------
// Tall-skinny GEMM via warp-level tf32 mma.sync (round-13 proven core, plus a
// row-offset for chunked pipelining):  in[t,s] = sum_j S[t,j] * C[s,j]
// ---------------------------------------------------------------------------
template <int NIN, int NCH>
__device__ __forceinline__ void gemm_body(const float* __restrict__ Sg,
                                          const float* __restrict__ Cg,
                                          float* __restrict__ outg,
                                          float* __restrict__ S_sh,
                                          float* __restrict__ C_sh,
                                          int t_base) {
    const int tid = threadIdx.x;
    const int wid = tid >> 5;
    const int lid = tid & 31;
    const int gr = lid >> 2;          // groupID (0..7)
    const int tg = lid & 3;           // threadID_in_group (0..3)
    const int t0 = t_base + blockIdx.x * 128;

    const uint32_t s_base = smem_u32(S_sh);
    const uint32_t c_base = smem_u32(C_sh);

#define STAGE(BUF, CH)                                                        \
    {                                                                         \
        const int kc = (CH) * 32;                                             \
        _Pragma("unroll")                                                     \
        for (int q = 0; q < 4; q++) {                                         \
            int g = q * GTH + tid;                                            \
            int r = g >> 3, cg = g & 7;                                       \
            int col = kc + cg * 4;                                            \
            bool okg = ((t0 + r) < T_DATA) && (col < NIN);                    \
            cpa16(s_base + (uint32_t)(((BUF) * S_WORDS + r * SSTR + cg * 4) * 4), \
                  Sg + (size_t)(okg ? (t0 + r) : 0) * NIN + (okg ? col : 0),  \
                  okg);                                                       \
        }                                                                     \
        if (tid < 192) {                                                      \
            int r = tid >> 3, cg = tid & 7;                                   \
            int col = kc + cg * 4;                                            \
            bool okc = (r < SUB) && (col < NIN);                              \
            cpa16(c_base + (uint32_t)(((BUF) * C_WORDS + r * SSTR + cg * 4) * 4), \
                  Cg + (size_t)(okc ? r : 0) * NIN + (okc ? col : 0),         \
                  okc);                                                       \
        }                                                                     \
    }

    float d[3][4];
#pragma unroll
    for (int nt = 0; nt < 3; nt++)
#pragma unroll
        for (int r = 0; r < 4; r++) d[nt][r] = 0.f;

    STAGE(0, 0);
    asm volatile("cp.async.commit_group;");

    int buf = 0;
#pragma unroll 1
    for (int ch = 0; ch < NCH; ch++) {
        if (ch + 1 < NCH) STAGE(buf ^ 1, ch + 1);
        asm volatile("cp.async.commit_group;");
        asm volatile("cp.async.wait_group 1;");
        __syncthreads();                        // chunk ch resident

        const float* arow = S_sh + buf * S_WORDS + (wid * 16 + gr) * SSTR + tg;
        const float* brow = C_sh + buf * C_WORDS + gr * SSTR + tg;
#pragma unroll
        for (int ks = 0; ks < 4; ks++) {
            const int k0 = ks * 8;
            uint32_t a0 = to_tf32(arow[k0]);
            uint32_t a1 = to_tf32(arow[k0 + 8 * SSTR]);
            uint32_t a2 = to_tf32(arow[k0 + 4]);
            uint32_t a3 = to_tf32(arow[k0 + 4 + 8 * SSTR]);
#pragma unroll
            for (int nt = 0; nt < 3; nt++) {
                uint32_t b0 = to_tf32(brow[nt * 8 * SSTR + k0]);
                uint32_t b1 = to_tf32(brow[nt * 8 * SSTR + k0 + 4]);
                mma_tf32(d[nt], a0, a1, a2, a3, b0, b1);
            }
        }
        buf ^= 1;
        __syncthreads();                        // done reading old buf
    }
#undef STAGE

    const int tlo = t0 + wid * 16 + gr;
    const int thi = tlo + 8;
#pragma unroll
    for (int nt = 0; nt < 3; nt++) {
        int c0 = nt * 8 + 2 * tg;
        int c1 = c0 + 1;
        if (c0 < SUB) {
            if (tlo < T_DATA) outg[(size_t)c0 * T_DATA + tlo] = d[nt][0];
            if (thi < T_DATA) outg[(size_t)c0 * T_DATA + thi] = d[nt][2];
        }
        if (c1 < SUB) {
            if (tlo < T_DATA) outg[(size_t)c1 * T_DATA + tlo] = d[nt][1];
            if (thi < T_DATA) outg[(size_t)c1 * T_DATA + thi] = d[nt][3];
        }
    }
}

__global__ __launch_bounds__(GTH, 4)
void gemm_kernel(const float* __restrict__ Se, const float* __restrict__ Si,
                 const float* __restrict__ Ce, const float* __restrict__ Ci,
                 float* __restrict__ oe, float* __restrict__ oi, int t_base) {
    __shared__ __align__(16) float S_sh[2 * S_WORDS];   // 36864 B
    __shared__ __align__(16) float C_sh[2 * C_WORDS];   // 6912 B
    if (blockIdx.y == 0) gemm_body<N_E, 16>(Se, Ce, oe, S_sh, C_sh, t_base);
    else                 gemm_body<N_I, 7>(Si, Ci, oi, S_sh, C_sh, t_base);
}

// ---------------------------------------------------------------------------
// Causal conv (round-13 proven core, plus tile offset for pipelining).
// ---------------------------------------------------------------------------
__global__ __launch_bounds__(CTH, 10) void conv_kernel(float* __restrict__ out,
                                                       const float* __restrict__ K_syn,
                                                       const float* __restrict__ tau_syn,
                                                       const float* __restrict__ delta_syn,
                                                       int tile_off) {
    __shared__ ull sh[8 * NWC];
    __shared__ ull ksh[KP];

    const int s = blockIdx.y;
    const int t0 = (blockIdx.x + tile_off) * TTC;
    const int tid = threadIdx.x;
    const size_t sT = (size_t)s * T_DATA;

    for (int k = tid; k < KP; k += CTH) {
        float ae = 0.f, ai = 0.f;
        if (k < TSYN) {
            float tse = fmaxf((float)k - delta_syn[s * 2 + 0], 0.f);
            float tsi = fmaxf((float)k - delta_syn[s * 2 + 1], 0.f);
#pragma unroll
            for (int b = 0; b < NB; b++) {
                float te = tse / expf(tau_syn[b * 2 + 0]);
                float ti = tsi / expf(tau_syn[b * 2 + 1]);
                ae += K_syn[s * 6 + b * 2 + 0] * te * expf(-te);
                ai += K_syn[s * 6 + b * 2 + 1] * ti * expf(-ti);
            }
        }
        ksh[k] = pk2(ae, ai);
    }

    for (int Lp = tid; Lp < 8 * NWC; Lp += CTH) {
        int t = t0 - 208 + Lp;
        float e = 0.f, ii = 0.f;
        if (t >= 0 && t < T_DATA) { e = g_e[sT + t]; ii = g_i[sT + t]; }
        sh[(Lp & 7) * NWC + (Lp >> 3)] = pk2(e, ii);
    }
    __syncthreads();

#define AT(c) sh[(((c) & 7) * NWC) + tid + 1 + ((c) >> 3)]

    ull P[8], acc[8];
#pragma unroll
    for (int j = 0; j < 8; j++) {
        acc[j] = 0ULL;
        P[j] = AT(200 + j);
    }

#pragma unroll 2
    for (int kb = 0; kb < KP; kb += 8) {
#pragma unroll
        for (int r = 0; r < 8; r++) {
            ull kv = ksh[kb + r];
#pragma unroll
            for (int j = 0; j < 8; j++)
                fma2(acc[j], kv, P[(j - r) & 7]);
            P[7 - r] = AT(199 - kb - r);
        }
    }
#undef AT

#pragma unroll
    for (int j = 0; j < 8; j++) {
        int t = t0 + 8 * tid + j;
        if (t < T_DATA) {
            float lo, hi;
            upk2(acc[j], lo, hi);
            out[(size_t)t * SUB + s] = lo + hi;
        }
    }
}

// ---------------------------------------------------------------------------
// Chunked fork/join pipeline: gemm chunk j on the capture (default) stream,
// conv chunk j on a side stream gated by event eG[j]. Conv chunk j covers
// tiles < 25.6k*(j+1) rows == gemm rows completed through chunk j (conv's
// dependency is backward-looking only), so overlap is safe.
// ---------------------------------------------------------------------------
extern "C" void kernel_launch(void* const* d_in, const int* in_sizes, int n_in,
                              void* d_out, int out_size) {
    const float* S_e     = (const float*)d_in[0];
    const float* S_i     = (const float*)d_in[1];
    const float* C_syn_e = (const float*)d_in[2];
    const float* C_syn_i = (const float*)d_in[3];
    const float* K_syn   = (const float*)d_in[4];
    const float* tau_syn = (const float*)d_in[5];
    const float* delta   = (const float*)d_in[6];
    float* out = (float*)d_out;

    (void)in_sizes; (void)n_in; (void)out_size;

    float* ge; cudaGetSymbolAddress((void**)&ge, g_e);
    float* gi; cudaGetSymbolAddress((void**)&gi, g_i);

    static cudaStream_t sC = nullptr;
    static cudaEvent_t e0 = nullptr, eG[NSPLIT], eC = nullptr;
    if (sC == nullptr) {
        cudaStreamCreateWithFlags(&sC, cudaStreamNonBlocking);
        cudaEventCreateWithFlags(&e0, cudaEventDisableTiming);
        for (int j = 0; j < NSPLIT; j++)
            cudaEventCreateWithFlags(&eG[j], cudaEventDisableTiming);
        cudaEventCreateWithFlags(&eC, cudaEventDisableTiming);
    }

    // gemm chunks: blocks of 128 rows; conv chunks: tiles of 1024 rows.
    // (gj*128) cumulative == (cj*1024) cumulative at every boundary.
    const int gchunk[NSPLIT] = {200, 200, 200, 182};   // 782 blocks total
    const int cchunk[NSPLIT] = {25, 25, 25, 23};       // 98 tiles total

    // fork side stream into the capture graph
    cudaEventRecord(e0, 0);
    cudaStreamWaitEvent(sC, e0, 0);

    int goff = 0, coff = 0;
    for (int j = 0; j < NSPLIT; j++) {
        gemm_kernel<<<dim3(gchunk[j], 2), GTH>>>(S_e, S_i, C_syn_e, C_syn_i,
                                                 ge, gi, goff * 128);
        cudaEventRecord(eG[j], 0);
        cudaStreamWaitEvent(sC, eG[j], 0);
        conv_kernel<<<dim3(cchunk[j], SUB), CTH, 0, sC>>>(out, K_syn, tau_syn,
                                                          delta, coff);
        goff += gchunk[j];
        coff += cchunk[j];
    }

    // join side stream back into the capture stream
    cudaEventRecord(eC, sC);
    cudaStreamWaitEvent(0, eC, 0);
}

// round 16
// speedup vs baseline: 1.4439x; 1.4439x over previous
#include <cuda_runtime.h>
#include <cstdint>

#define T_DATA 100000
#define N_E    500
#define N_I    200
#define SUB    20
#define NB     3
#define TSYN   201

typedef unsigned long long ull;

// ---- GEMM config ----
#define GTH    256                 // 8 warps x 16 rows = 128 rows/block
#define SSTR   36                  // smem row stride in words (== 4 mod 32)
#define S_WORDS (128 * SSTR)       // 4608 floats per S buffer
#define C_WORDS (24 * SSTR)        // 864 floats per C buffer

// ---- conv config ----
#define CTH   128
#define TTC   1024
#define KP    208
#define NWC   154

// Scratch (device globals: allocation-free rule)
__device__ float g_e[(size_t)SUB * T_DATA];
__device__ float g_i[(size_t)SUB * T_DATA];

// ---- packed f32x2 helpers (conv) ----
__device__ __forceinline__ ull pk2(float lo, float hi) {
    ull r;
    asm("mov.b64 %0, {%1, %2};" : "=l"(r) : "f"(lo), "f"(hi));
    return r;
}
__device__ __forceinline__ void upk2(ull v, float& lo, float& hi) {
    asm("mov.b64 {%0, %1}, %2;" : "=f"(lo), "=f"(hi) : "l"(v));
}
__device__ __forceinline__ void fma2(ull& d, ull a, ull b) {
    asm("fma.rn.f32x2 %0, %1, %2, %0;" : "+l"(d) : "l"(a), "l"(b));
}

// ---- GEMM helpers ----
__device__ __forceinline__ uint32_t smem_u32(const void* p) {
    return (uint32_t)__cvta_generic_to_shared(p);
}
__device__ __forceinline__ void cpa16(uint32_t dst, const void* src, bool ok) {
    int sz = ok ? 16 : 0;
    asm volatile("cp.async.cg.shared.global [%0], [%1], 16, %2;"
                 :: "r"(dst), "l"(src), "r"(sz));
}
__device__ __forceinline__ uint32_t to_tf32(float f) {
    uint32_t u;
    asm("cvt.rna.tf32.f32 %0, %1;" : "=r"(u) : "f"(f));
    return u;
}
__device__ __forceinline__ void mma_tf32(float* d, uint32_t a0, uint32_t a1,
                                         uint32_t a2, uint32_t a3,
                                         uint32_t b0, uint32_t b1) {
    asm volatile(
        "mma.sync.aligned.m16n8k8.row.col.f32.tf32.tf32.f32 "
        "{%0,%1,%2,%3}, {%4,%5,%6,%7}, {%8,%9}, {%0,%1,%2,%3};"
        : "+f"(d[0]), "+f"(d[1]), "+f"(d[2]), "+f"(d[3])
        : "r"(a0), "r"(a1), "r"(a2), "r"(a3), "r"(b0), "r"(b1));
}

// ---------------------------------------------------------------------------
// Tall-skinny GEMM via warp-level tf32 mma.sync (round-13 proven core):
//   in[t,s] = sum_j S[t,j] * C[s,j]
// M = time (16/warp), N = subunits (20 -> 24, 3 n8-tiles), K chunks of 32
// (4 ksteps), K/N zero-padded through cp.async src_size=0.
// Smem rows stride 36 words (==4 mod 32): A-frag and B-frag scalar LDS are
// perfect 32-bank permutations. cvt.rna.tf32 at fragment load.
// ---------------------------------------------------------------------------
template <int NIN, int NCH>
__device__ __forceinline__ void gemm_body(const float* __restrict__ Sg,
                                          const float* __restrict__ Cg,
                                          float* __restrict__ outg,
                                          float* __restrict__ S_sh,
                                          float* __restrict__ C_sh) {
    const int tid = threadIdx.x;
    const int wid = tid >> 5;
    const int lid = tid & 31;
    const int gr = lid >> 2;          // groupID (0..7)
    const int tg = lid & 3;           // threadID_in_group (0..3)
    const int t0 = blockIdx.x * 128;

    const uint32_t s_base = smem_u32(S_sh);
    const uint32_t c_base = smem_u32(C_sh);

#define STAGE(BUF, CH)                                                        \
    {                                                                         \
        const int kc = (CH) * 32;                                             \
        _Pragma("unroll")                                                     \
        for (int q = 0; q < 4; q++) {                                         \
            int g = q * GTH + tid;                                            \
            int r = g >> 3, cg = g & 7;                                       \
            int col = kc + cg * 4;                                            \
            bool okg = ((t0 + r) < T_DATA) && (col < NIN);                    \
            cpa16(s_base + (uint32_t)(((BUF) * S_WORDS + r * SSTR + cg * 4) * 4), \
                  Sg + (size_t)(okg ? (t0 + r) : 0) * NIN + (okg ? col : 0),  \
                  okg);                                                       \
        }                                                                     \
        if (tid < 192) {                                                      \
            int r = tid >> 3, cg = tid & 7;                                   \
            int col = kc + cg * 4;                                            \
            bool okc = (r < SUB) && (col < NIN);                              \
            cpa16(c_base + (uint32_t)(((BUF) * C_WORDS + r * SSTR + cg * 4) * 4), \
                  Cg + (size_t)(okc ? r : 0) * NIN + (okc ? col : 0),         \
                  okc);                                                       \
        }                                                                     \
    }

    float d[3][4];
#pragma unroll
    for (int nt = 0; nt < 3; nt++)
#pragma unroll
        for (int r = 0; r < 4; r++) d[nt][r] = 0.f;

    STAGE(0, 0);
    asm volatile("cp.async.commit_group;");

    int buf = 0;
#pragma unroll 1
    for (int ch = 0; ch < NCH; ch++) {
        if (ch + 1 < NCH) STAGE(buf ^ 1, ch + 1);
        asm volatile("cp.async.commit_group;");
        asm volatile("cp.async.wait_group 1;");
        __syncthreads();                        // chunk ch resident

        const float* arow = S_sh + buf * S_WORDS + (wid * 16 + gr) * SSTR + tg;
        const float* brow = C_sh + buf * C_WORDS + gr * SSTR + tg;
#pragma unroll
        for (int ks = 0; ks < 4; ks++) {
            const int k0 = ks * 8;
            uint32_t a0 = to_tf32(arow[k0]);
            uint32_t a1 = to_tf32(arow[k0 + 8 * SSTR]);
            uint32_t a2 = to_tf32(arow[k0 + 4]);
            uint32_t a3 = to_tf32(arow[k0 + 4 + 8 * SSTR]);
#pragma unroll
            for (int nt = 0; nt < 3; nt++) {
                uint32_t b0 = to_tf32(brow[nt * 8 * SSTR + k0]);
                uint32_t b1 = to_tf32(brow[nt * 8 * SSTR + k0 + 4]);
                mma_tf32(d[nt], a0, a1, a2, a3, b0, b1);
            }
        }
        buf ^= 1;
        __syncthreads();                        // done reading old buf
    }
#undef STAGE

    const int tlo = t0 + wid * 16 + gr;
    const int thi = tlo + 8;
#pragma unroll
    for (int nt = 0; nt < 3; nt++) {
        int c0 = nt * 8 + 2 * tg;
        int c1 = c0 + 1;
        if (c0 < SUB) {
            if (tlo < T_DATA) outg[(size_t)c0 * T_DATA + tlo] = d[nt][0];
            if (thi < T_DATA) outg[(size_t)c0 * T_DATA + thi] = d[nt][2];
        }
        if (c1 < SUB) {
            if (tlo < T_DATA) outg[(size_t)c1 * T_DATA + tlo] = d[nt][1];
            if (thi < T_DATA) outg[(size_t)c1 * T_DATA + thi] = d[nt][3];
        }
    }
}

__global__ __launch_bounds__(GTH, 5)
void gemm_kernel(const float* __restrict__ Se, const float* __restrict__ Si,
                 const float* __restrict__ Ce, const float* __restrict__ Ci,
                 float* __restrict__ oe, float* __restrict__ oi) {
    __shared__ __align__(16) float S_sh[2 * S_WORDS];   // 36864 B
    __shared__ __align__(16) float C_sh[2 * C_WORDS];   // 6912 B
    if (blockIdx.y == 0) gemm_body<N_E, 16>(Se, Ce, oe, S_sh, C_sh);
    else                 gemm_body<N_I, 7>(Si, Ci, oi, S_sh, C_sh);
}

// ---------------------------------------------------------------------------
// Causal conv (round-13 proven core): e/i fused via f32x2 lanes, register
// sliding window, residue-of-8 smem layout. launch_bounds bumped to 12
// blocks/SM (reg cap 42) to cut wave quantization: capacity 1480 -> 1776
// blocks, waves 1.32 -> 1.10.
// ---------------------------------------------------------------------------
__global__ __launch_bounds__(CTH, 12) void conv_kernel(float* __restrict__ out,
                                                       const float* __restrict__ K_syn,
                                                       const float* __restrict__ tau_syn,
                                                       const float* __restrict__ delta_syn) {
    __shared__ ull sh[8 * NWC];
    __shared__ ull ksh[KP];

    const int s = blockIdx.y;
    const int t0 = blockIdx.x * TTC;
    const int tid = threadIdx.x;
    const size_t sT = (size_t)s * T_DATA;

    for (int k = tid; k < KP; k += CTH) {
        float ae = 0.f, ai = 0.f;
        if (k < TSYN) {
            float tse = fmaxf((float)k - delta_syn[s * 2 + 0], 0.f);
            float tsi = fmaxf((float)k - delta_syn[s * 2 + 1], 0.f);
#pragma unroll
            for (int b = 0; b < NB; b++) {
                float te = tse / expf(tau_syn[b * 2 + 0]);
                float ti = tsi / expf(tau_syn[b * 2 + 1]);
                ae += K_syn[s * 6 + b * 2 + 0] * te * expf(-te);
                ai += K_syn[s * 6 + b * 2 + 1] * ti * expf(-ti);
            }
        }
        ksh[k] = pk2(ae, ai);
    }

    for (int Lp = tid; Lp < 8 * NWC; Lp += CTH) {
        int t = t0 - 208 + Lp;
        float e = 0.f, ii = 0.f;
        if (t >= 0 && t < T_DATA) { e = g_e[sT + t]; ii = g_i[sT + t]; }
        sh[(Lp & 7) * NWC + (Lp >> 3)] = pk2(e, ii);
    }
    __syncthreads();

#define AT(c) sh[(((c) & 7) * NWC) + tid + 1 + ((c) >> 3)]

    ull P[8], acc[8];
#pragma unroll
    for (int j = 0; j < 8; j++) {
        acc[j] = 0ULL;
        P[j] = AT(200 + j);
    }

#pragma unroll 2
    for (int kb = 0; kb < KP; kb += 8) {
#pragma unroll
        for (int r = 0; r < 8; r++) {
            ull kv = ksh[kb + r];
#pragma unroll
            for (int j = 0; j < 8; j++)
                fma2(acc[j], kv, P[(j - r) & 7]);
            P[7 - r] = AT(199 - kb - r);
        }
    }
#undef AT

#pragma unroll
    for (int j = 0; j < 8; j++) {
        int t = t0 + 8 * tid + j;
        if (t < T_DATA) {
            float lo, hi;
            upk2(acc[j], lo, hi);
            out[(size_t)t * SUB + s] = lo + hi;
        }
    }
}

// ---------------------------------------------------------------------------
extern "C" void kernel_launch(void* const* d_in, const int* in_sizes, int n_in,
                              void* d_out, int out_size) {
    const float* S_e     = (const float*)d_in[0];
    const float* S_i     = (const float*)d_in[1];
    const float* C_syn_e = (const float*)d_in[2];
    const float* C_syn_i = (const float*)d_in[3];
    const float* K_syn   = (const float*)d_in[4];
    const float* tau_syn = (const float*)d_in[5];
    const float* delta   = (const float*)d_in[6];
    float* out = (float*)d_out;

    (void)in_sizes; (void)n_in; (void)out_size;

    float* ge; cudaGetSymbolAddress((void**)&ge, g_e);
    float* gi; cudaGetSymbolAddress((void**)&gi, g_i);

    dim3 ggrid((T_DATA + 127) / 128, 2);            // 782 x 2 (e and i)
    gemm_kernel<<<ggrid, GTH>>>(S_e, S_i, C_syn_e, C_syn_i, ge, gi);

    dim3 cgrid((T_DATA + TTC - 1) / TTC, SUB);      // 98 x 20
    conv_kernel<<<cgrid, CTH>>>(out, K_syn, tau_syn, delta);
}